// round 7
// baseline (speedup 1.0000x reference)
#include <cuda_runtime.h>

// Problem constants
#define BB 128
#define TT 2048
#define LL 8              // timesteps per chunk
#define CC (TT / LL)      // 256 chunks per batch
#define NM (BB * TT)      // 262144 matrices total
#define DT 0.02f

// Scratch: 32 floats per 4x4 complex matrix = [re[16], im[16]] = 8 float4 (128B)
__device__ __align__(128) float4 g_U[(size_t)NM * 8];        // 33.5 MB: all unitaries
__device__ __align__(128) float4 g_P[(size_t)BB * CC * 8];   // chunk products
__device__ __align__(128) float4 g_S[(size_t)BB * CC * 8];   // incoming state per chunk

// ---------------------------------------------------------------------------
// Packed f32x2 primitives (FFMA2 — only reachable via PTX)
typedef unsigned long long u64p;

__device__ __forceinline__ u64p pk2(float x, float y) {
    u64p r; asm("mov.b64 %0, {%1, %2};" : "=l"(r) : "f"(x), "f"(y)); return r;
}
__device__ __forceinline__ void upk2(u64p v, float& x, float& y) {
    asm("mov.b64 {%0, %1}, %2;" : "=f"(x), "=f"(y) : "l"(v));
}
__device__ __forceinline__ u64p psplat(float a) { return pk2(a, a); }
__device__ __forceinline__ u64p pfma(u64p a, u64p b, u64p c) {
    u64p r; asm("fma.rn.f32x2 %0, %1, %2, %3;" : "=l"(r) : "l"(a), "l"(b), "l"(c)); return r;
}
__device__ __forceinline__ u64p pmul(u64p a, u64p b) {
    u64p r; asm("mul.rn.f32x2 %0, %1, %2;" : "=l"(r) : "l"(a), "l"(b)); return r;
}
__device__ __forceinline__ u64p padd(u64p a, u64p b) {
    u64p r; asm("add.rn.f32x2 %0, %1, %2;" : "=l"(r) : "l"(a), "l"(b)); return r;
}

struct PRow { u64p r01, r23, i01, i23; };

__device__ __forceinline__ void caccum(float a, float b, const PRow& y, PRow& z) {
    u64p sa = psplat(a), sb = psplat(b), snb = psplat(-b);
    z.r01 = pfma(sa, y.r01, pfma(snb, y.i01, z.r01));
    z.r23 = pfma(sa, y.r23, pfma(snb, y.i23, z.r23));
    z.i01 = pfma(sa, y.i01, pfma(sb, y.r01, z.i01));
    z.i23 = pfma(sa, y.i23, pfma(sb, y.r23, z.i23));
}

template <bool ZERO>
__device__ __forceinline__ void pcmm(const PRow* __restrict__ x, const PRow* __restrict__ y,
                                     PRow* __restrict__ z) {
#pragma unroll
    for (int i = 0; i < 4; ++i) {
        if (ZERO) { z[i].r01 = pk2(0, 0); z[i].r23 = pk2(0, 0); z[i].i01 = pk2(0, 0); z[i].i23 = pk2(0, 0); }
        float er0, er1, er2, er3, ei0, ei1, ei2, ei3;
        upk2(x[i].r01, er0, er1); upk2(x[i].r23, er2, er3);
        upk2(x[i].i01, ei0, ei1); upk2(x[i].i23, ei2, ei3);
        caccum(er0, ei0, y[0], z[i]);
        caccum(er1, ei1, y[1], z[i]);
        caccum(er2, ei2, y[2], z[i]);
        caccum(er3, ei3, y[3], z[i]);
    }
}

// ---------------------------------------------------------------------------
// Scalar helpers
__device__ __forceinline__ void cax4(float a, float b, float4 cr, float4 ci,
                                     float4& accr, float4& acci) {
    accr.x = fmaf(a, cr.x, fmaf(-b, ci.x, accr.x));
    acci.x = fmaf(a, ci.x, fmaf( b, cr.x, acci.x));
    accr.y = fmaf(a, cr.y, fmaf(-b, ci.y, accr.y));
    acci.y = fmaf(a, ci.y, fmaf( b, cr.y, acci.y));
    accr.z = fmaf(a, cr.z, fmaf(-b, ci.z, accr.z));
    acci.z = fmaf(a, ci.z, fmaf( b, cr.z, acci.z));
    accr.w = fmaf(a, cr.w, fmaf(-b, ci.w, accr.w));
    acci.w = fmaf(a, ci.w, fmaf( b, cr.w, acci.w));
}

// row (ur,ui) dot column (sr,si) -> (or_, oi_)
__device__ __forceinline__ void rowdot(float4 ur, float4 ui, const float* __restrict__ sr,
                                       const float* __restrict__ si, float& or_, float& oi_) {
    float xr = 0.0f, xi = 0.0f;
    xr = fmaf(ur.x, sr[0], fmaf(-ui.x, si[0], xr)); xi = fmaf(ur.x, si[0], fmaf(ui.x, sr[0], xi));
    xr = fmaf(ur.y, sr[1], fmaf(-ui.y, si[1], xr)); xi = fmaf(ur.y, si[1], fmaf(ui.y, sr[1], xi));
    xr = fmaf(ur.z, sr[2], fmaf(-ui.z, si[2], xr)); xi = fmaf(ur.z, si[2], fmaf(ui.z, sr[2], xi));
    xr = fmaf(ur.w, sr[3], fmaf(-ui.w, si[3], xr)); xi = fmaf(ur.w, si[3], fmaf(ui.w, sr[3], xi));
    or_ = xr; oi_ = xi;
}

// shuffle one full float4-pair row from lane `src` (every lane passes its own row)
__device__ __forceinline__ void shfl_row(float4 pr, float4 pim, int src,
                                         float4& outr, float4& outi) {
    outr.x = __shfl_sync(0xffffffffu, pr.x, src);
    outr.y = __shfl_sync(0xffffffffu, pr.y, src);
    outr.z = __shfl_sync(0xffffffffu, pr.z, src);
    outr.w = __shfl_sync(0xffffffffu, pr.w, src);
    outi.x = __shfl_sync(0xffffffffu, pim.x, src);
    outi.y = __shfl_sync(0xffffffffu, pim.y, src);
    outi.z = __shfl_sync(0xffffffffu, pim.z, src);
    outi.w = __shfl_sync(0xffffffffu, pim.w, src);
}

// ---------------------------------------------------------------------------
// K0: U = expm(-i*dt*H), degree-4 Taylor via packed f32x2, with FUSED
// chunk-product tail spread over ALL 128 threads:
//   item = (chunk cl2, column j, row-half h); partner (tid^1) holds other half.
// smem U copy: chunk cl stride 65 quads; quad q of matrix l at cl*65+l*8+(q^l).
__global__ void __launch_bounds__(128) k_expm(const float* __restrict__ hr_g,
                                              const float* __restrict__ hi_g) {
    __shared__ float4 sUc[16 * 65];          // 16,640 B

    int tid = threadIdx.x;
    int idx = blockIdx.x * 128 + tid;

    const float4* hr4 = reinterpret_cast<const float4*>(hr_g) + (size_t)idx * 4;
    const float4* hi4 = reinterpret_cast<const float4*>(hi_g) + (size_t)idx * 4;

    // A = dt*hi - i*dt*hr
    PRow A[4];
    const u64p pdt = psplat(DT), pndt = psplat(-DT);
#pragma unroll
    for (int i = 0; i < 4; ++i) {
        float4 r = hr4[i], m = hi4[i];
        A[i].r01 = pmul(pdt,  pk2(m.x, m.y));
        A[i].r23 = pmul(pdt,  pk2(m.z, m.w));
        A[i].i01 = pmul(pndt, pk2(r.x, r.y));
        A[i].i23 = pmul(pndt, pk2(r.z, r.w));
    }

    PRow B[4];                   // A^2
    pcmm<true>(A, A, B);

    // M = I/2 + A/6 + A^2/24
    PRow M[4];
    const u64p c6 = psplat(1.0f / 6.0f), c24 = psplat(1.0f / 24.0f);
#pragma unroll
    for (int i = 0; i < 4; ++i) {
        M[i].r01 = pfma(c6, A[i].r01, pmul(c24, B[i].r01));
        M[i].r23 = pfma(c6, A[i].r23, pmul(c24, B[i].r23));
        M[i].i01 = pfma(c6, A[i].i01, pmul(c24, B[i].i01));
        M[i].i23 = pfma(c6, A[i].i23, pmul(c24, B[i].i23));
    }
    M[0].r01 = padd(M[0].r01, pk2(0.5f, 0.0f));
    M[1].r01 = padd(M[1].r01, pk2(0.0f, 0.5f));
    M[2].r23 = padd(M[2].r23, pk2(0.5f, 0.0f));
    M[3].r23 = padd(M[3].r23, pk2(0.0f, 0.5f));

    // E = A + B*M  (into A), then +I
    pcmm<false>(B, M, A);
    A[0].r01 = padd(A[0].r01, pk2(1.0f, 0.0f));
    A[1].r01 = padd(A[1].r01, pk2(0.0f, 1.0f));
    A[2].r23 = padd(A[2].r23, pk2(1.0f, 0.0f));
    A[3].r23 = padd(A[3].r23, pk2(0.0f, 1.0f));

    // Unpack to float4 quads; store to global AND smem (swizzled)
    float4 q[8];
#pragma unroll
    for (int i = 0; i < 4; ++i) {
        float x0, x1, x2, x3, y0, y1, y2, y3;
        upk2(A[i].r01, x0, x1); upk2(A[i].r23, x2, x3);
        upk2(A[i].i01, y0, y1); upk2(A[i].i23, y2, y3);
        q[i]     = make_float4(x0, x1, x2, x3);
        q[4 + i] = make_float4(y0, y1, y2, y3);
    }
    float4* Up = g_U + (size_t)idx * 8;
    {
        int cl = tid >> 3, l = tid & 7;
        float4* Sp = sUc + cl * 65 + l * 8;
#pragma unroll
        for (int k = 0; k < 8; ++k) {
            Up[k] = q[k];
            Sp[k ^ l] = q[k];
        }
    }
    __syncthreads();

    // ---- chunk product tail: 128 threads = 16 chunks x 4 cols x 2 halves
    {
        int cl2 = tid >> 3;
        int j   = (tid >> 1) & 3;
        int h   = tid & 1;
        int r0  = 2 * h, r1 = 2 * h + 1;

        float a0r = (j == r0) ? 1.0f : 0.0f, a0i = 0.0f;
        float a1r = (j == r1) ? 1.0f : 0.0f, a1i = 0.0f;

        const float4* Ub = sUc + cl2 * 65;
#pragma unroll
        for (int l2 = 0; l2 < LL; ++l2) {
            float p0r = __shfl_xor_sync(0xffffffffu, a0r, 1);
            float p0i = __shfl_xor_sync(0xffffffffu, a0i, 1);
            float p1r = __shfl_xor_sync(0xffffffffu, a1r, 1);
            float p1i = __shfl_xor_sync(0xffffffffu, a1i, 1);

            float fsr[4], fsi[4];
            fsr[0] = h ? p0r : a0r;  fsi[0] = h ? p0i : a0i;
            fsr[1] = h ? p1r : a1r;  fsi[1] = h ? p1i : a1i;
            fsr[2] = h ? a0r : p0r;  fsi[2] = h ? a0i : p0i;
            fsr[3] = h ? a1r : p1r;  fsi[3] = h ? a1i : p1i;

            const float4* Um = Ub + l2 * 8;
            float4 u0r = Um[r0 ^ l2],       u1r = Um[r1 ^ l2];
            float4 u0i = Um[(4 + r0) ^ l2], u1i = Um[(4 + r1) ^ l2];
            rowdot(u0r, u0i, fsr, fsi, a0r, a0i);
            rowdot(u1r, u1i, fsr, fsi, a1r, a1i);
        }

        int chunk = blockIdx.x * 16 + cl2;
        float* Pp = reinterpret_cast<float*>(g_P) + (size_t)chunk * 32;
        Pp[r0 * 4 + j] = a0r;       Pp[r1 * 4 + j] = a1r;
        Pp[16 + r0 * 4 + j] = a0i;  Pp[16 + r1 * 4 + j] = a1i;
    }
}

// ---------------------------------------------------------------------------
// K2: TWO-LEVEL row-parallel scan per batch. 1024 threads = 256 chunks x 4 rows.
// L1: warp-local KS over 8 chunks via shfl (no barriers).
// L2: KS over the 32 group totals, 128 threads, double-buffered padded smem.
// Final: inclusive = Q_e * G_{g-1}; V_e = Prefix_{e-1} * S0.
#define TOFF 288   // T_B offset (T matrices stride 9 quads; 32*9=288 per buffer)

__global__ void __launch_bounds__(1024) k_scan(const float* __restrict__ s0r_g,
                                               const float* __restrict__ s0i_g) {
    __shared__ float4 sh[CC * 12];   // 48KB; quads [0,576) double as T_A/T_B
    int b = blockIdx.x;
    int tid = threadIdx.x;
    int e = tid >> 2, i = tid & 3;
    int lane = tid & 31;
    int el = lane >> 2;              // local chunk within warp (0..7)
    int g = e >> 3;                  // group (= warp id, 0..31)

    const float4* Pg = g_P + ((size_t)b * CC + e) * 8;
    float4 pr = Pg[i], pim = Pg[4 + i];

    // ---- L1: warp-local KS over 8 (rows fetched via shfl)
#pragma unroll
    for (int d = 1; d < 8; d <<= 1) {
        int srcb = ((el >= d) ? (el - d) : 0) << 2;
        float4 l0r, l0i, l1r, l1i, l2r, l2i, l3r, l3i;
        shfl_row(pr, pim, srcb + 0, l0r, l0i);
        shfl_row(pr, pim, srcb + 1, l1r, l1i);
        shfl_row(pr, pim, srcb + 2, l2r, l2i);
        shfl_row(pr, pim, srcb + 3, l3r, l3i);
        if (el >= d) {
            float4 nr = make_float4(0, 0, 0, 0), ni = make_float4(0, 0, 0, 0);
            cax4(pr.x, pim.x, l0r, l0i, nr, ni);
            cax4(pr.y, pim.y, l1r, l1i, nr, ni);
            cax4(pr.z, pim.z, l2r, l2i, nr, ni);
            cax4(pr.w, pim.w, l3r, l3i, nr, ni);
            pr = nr; pim = ni;
        }
    }

    // ---- publish group totals (el==7) into T_A (stride 9 quads per matrix)
    if (el == 7) {
        sh[g * 9 + i] = pr;
        sh[g * 9 + 4 + i] = pim;
    }
    __syncthreads();

    // ---- L2: KS over 32 totals, 128 threads, 5 rounds, double-buffered
    if (tid < 128) {
        int g2 = tid >> 2, i2 = tid & 3;
        int rb = 0;
#pragma unroll
        for (int d = 1; d < 32; d <<= 1) {
            const float4* src = sh + rb;
            float4* dst = sh + (TOFF - rb);
            float4 qr = src[g2 * 9 + i2], qi = src[g2 * 9 + 4 + i2];
            if (g2 >= d) {
                const float4* nb = src + (size_t)(g2 - d) * 9;
                float4 nr = make_float4(0, 0, 0, 0), ni = make_float4(0, 0, 0, 0);
                cax4(qr.x, qi.x, nb[0], nb[4], nr, ni);
                cax4(qr.y, qi.y, nb[1], nb[5], nr, ni);
                cax4(qr.z, qi.z, nb[2], nb[6], nr, ni);
                cax4(qr.w, qi.w, nb[3], nb[7], nr, ni);
                qr = nr; qi = ni;
            }
            dst[g2 * 9 + i2] = qr;
            dst[g2 * 9 + 4 + i2] = qi;
            asm volatile("bar.sync 1, 128;" ::: "memory");
            rb = TOFF - rb;
        }
    }
    __syncthreads();
    // G (inclusive group prefixes) now at sh + TOFF (5 rounds: 0->288 ends at 288)

    // ---- inclusive prefix: Q_e * G_{g-1}
    if (g > 0) {
        const float4* nb = sh + TOFF + (size_t)(g - 1) * 9;
        float4 nr = make_float4(0, 0, 0, 0), ni = make_float4(0, 0, 0, 0);
        cax4(pr.x, pim.x, nb[0], nb[4], nr, ni);
        cax4(pr.y, pim.y, nb[1], nb[5], nr, ni);
        cax4(pr.z, pim.z, nb[2], nb[6], nr, ni);
        cax4(pr.w, pim.w, nb[3], nb[7], nr, ni);
        pr = nr; pim = ni;
    }
    __syncthreads();   // everyone done reading T before overwriting sh below

    // ---- publish inclusive rows (XOR-swizzled layout)
    int es = e & 7;
    {
        float4* me = sh + e * 12;
        me[i ^ es] = pr;
        me[(4 + i) ^ es] = pim;
    }
    __syncthreads();

    // ---- V_e = Prefix_{e-1} * S0  (V_0 = S0)
    const float4* r4 = reinterpret_cast<const float4*>(s0r_g) + (size_t)b * 4;
    const float4* i4 = reinterpret_cast<const float4*>(s0i_g) + (size_t)b * 4;
    float4 s0r0 = r4[0], s0r1 = r4[1], s0r2 = r4[2], s0r3 = r4[3];
    float4 s0i0 = i4[0], s0i1 = i4[1], s0i2 = i4[2], s0i3 = i4[3];

    float4 vr, vi;
    if (e == 0) {
        vr = (i == 0) ? s0r0 : (i == 1) ? s0r1 : (i == 2) ? s0r2 : s0r3;
        vi = (i == 0) ? s0i0 : (i == 1) ? s0i1 : (i == 2) ? s0i2 : s0i3;
    } else {
        int ens = (e - 1) & 7;
        const float4* nb = sh + (e - 1) * 12;
        float4 qr = nb[i ^ ens];
        float4 qi = nb[(4 + i) ^ ens];
        vr = make_float4(0, 0, 0, 0); vi = make_float4(0, 0, 0, 0);
        cax4(qr.x, qi.x, s0r0, s0i0, vr, vi);
        cax4(qr.y, qi.y, s0r1, s0i1, vr, vi);
        cax4(qr.z, qi.z, s0r2, s0i2, vr, vi);
        cax4(qr.w, qi.w, s0r3, s0i3, vr, vi);
    }
    float4* Sg = g_S + ((size_t)b * CC + e) * 8;
    Sg[i] = vr;
    Sg[4 + i] = vi;
}

// ---------------------------------------------------------------------------
// K3: ROW-parallel apply, BATCH-MAJOR mapping: warp's 8 chunk-groups are 8
// consecutive b with the same c -> each STG.128 is part of a 512B-contiguous
// warp store. State in smem double-buffered, stride 13 (conflict-free).
#define SSTR 13

__global__ void __launch_bounds__(128) k_apply(float* __restrict__ out) {
    __shared__ float4 sS[2][32 * SSTR];      // 13,312 B

    int tid = threadIdx.x;
    int cl = tid >> 2, i = tid & 3;
    int gidx = blockIdx.x * 32 + cl;         // b-fast ordering
    int b = gidx & (BB - 1);
    int c = gidx >> 7;                       // / BB
    int idx = b * CC + c;                    // chunk index in g_U/g_S

    {   // stage incoming state rows
        const float4* Sg = g_S + (size_t)idx * 8;
        sS[0][cl * SSTR + i] = Sg[i];
        sS[0][cl * SSTR + 4 + i] = Sg[4 + i];
    }

    const float4* Ug = g_U + (size_t)idx * 64;
    float4 ur = Ug[i], ui = Ug[4 + i];       // prefetch l=0

    __syncwarp();

    const size_t imag_off = (size_t)TT * BB * 16;
    float* ob = out + (((size_t)c * LL) * BB + b) * 16 + i * 4;

#pragma unroll
    for (int l = 0; l < LL; ++l) {
        float4 nur, nui;
        if (l < LL - 1) {
            nur = Ug[(l + 1) * 8 + i];
            nui = Ug[(l + 1) * 8 + 4 + i];
        }

        const int cur = l & 1;
        float4 s0r = sS[cur][cl * SSTR + 0];
        float4 s1r = sS[cur][cl * SSTR + 1];
        float4 s2r = sS[cur][cl * SSTR + 2];
        float4 s3r = sS[cur][cl * SSTR + 3];
        float4 s0i = sS[cur][cl * SSTR + 4];
        float4 s1i = sS[cur][cl * SSTR + 5];
        float4 s2i = sS[cur][cl * SSTR + 6];
        float4 s3i = sS[cur][cl * SSTR + 7];

        float4 nr = make_float4(0, 0, 0, 0), ni = make_float4(0, 0, 0, 0);
        cax4(ur.x, ui.x, s0r, s0i, nr, ni);
        cax4(ur.y, ui.y, s1r, s1i, nr, ni);
        cax4(ur.z, ui.z, s2r, s2i, nr, ni);
        cax4(ur.w, ui.w, s3r, s3i, nr, ni);

        if (l < LL - 1) {
            sS[cur ^ 1][cl * SSTR + i] = nr;
            sS[cur ^ 1][cl * SSTR + 4 + i] = ni;
        }

        float* op = ob + (size_t)l * BB * 16;
        __stcs(reinterpret_cast<float4*>(op), nr);
        __stcs(reinterpret_cast<float4*>(op + imag_off), ni);

        __syncwarp();
        ur = nur; ui = nui;
    }
}

// ---------------------------------------------------------------------------
extern "C" void kernel_launch(void* const* d_in, const int* in_sizes, int n_in,
                              void* d_out, int out_size) {
    const float* h_real = (const float*)d_in[0];
    const float* h_imag = (const float*)d_in[1];
    const float* s_real = (const float*)d_in[2];
    const float* s_imag = (const float*)d_in[3];
    float* out = (float*)d_out;

    k_expm<<<NM / 128, 128>>>(h_real, h_imag);
    k_scan<<<BB, CC * 4>>>(s_real, s_imag);
    k_apply<<<(BB * CC) / 32, 128>>>(out);
}

// round 8
// speedup vs baseline: 1.0146x; 1.0146x over previous
#include <cuda_runtime.h>

// Problem constants
#define BB 128
#define TT 2048
#define LL 8              // timesteps per chunk
#define CC (TT / LL)      // 256 chunks per batch
#define NM (BB * TT)      // 262144 matrices total
#define DT 0.02f

// Scratch: 32 floats per 4x4 complex matrix = [re[16], im[16]] = 8 float4 (128B)
__device__ __align__(128) float4 g_U[(size_t)NM * 8];        // 33.5 MB: all unitaries
__device__ __align__(128) float4 g_P[(size_t)BB * CC * 8];   // chunk products
__device__ __align__(128) float4 g_S[(size_t)BB * CC * 8];   // incoming state per chunk

// ---------------------------------------------------------------------------
// Packed f32x2 primitives (FFMA2 — only reachable via PTX)
typedef unsigned long long u64p;

__device__ __forceinline__ u64p pk2(float x, float y) {
    u64p r; asm("mov.b64 %0, {%1, %2};" : "=l"(r) : "f"(x), "f"(y)); return r;
}
__device__ __forceinline__ void upk2(u64p v, float& x, float& y) {
    asm("mov.b64 {%0, %1}, %2;" : "=f"(x), "=f"(y) : "l"(v));
}
__device__ __forceinline__ u64p psplat(float a) { return pk2(a, a); }
__device__ __forceinline__ u64p pfma(u64p a, u64p b, u64p c) {
    u64p r; asm("fma.rn.f32x2 %0, %1, %2, %3;" : "=l"(r) : "l"(a), "l"(b), "l"(c)); return r;
}
__device__ __forceinline__ u64p pmul(u64p a, u64p b) {
    u64p r; asm("mul.rn.f32x2 %0, %1, %2;" : "=l"(r) : "l"(a), "l"(b)); return r;
}
__device__ __forceinline__ u64p padd(u64p a, u64p b) {
    u64p r; asm("add.rn.f32x2 %0, %1, %2;" : "=l"(r) : "l"(a), "l"(b)); return r;
}

struct PRow { u64p r01, r23, i01, i23; };

__device__ __forceinline__ void caccum(float a, float b, const PRow& y, PRow& z) {
    u64p sa = psplat(a), sb = psplat(b), snb = psplat(-b);
    z.r01 = pfma(sa, y.r01, pfma(snb, y.i01, z.r01));
    z.r23 = pfma(sa, y.r23, pfma(snb, y.i23, z.r23));
    z.i01 = pfma(sa, y.i01, pfma(sb, y.r01, z.i01));
    z.i23 = pfma(sa, y.i23, pfma(sb, y.r23, z.i23));
}

template <bool ZERO>
__device__ __forceinline__ void pcmm(const PRow* __restrict__ x, const PRow* __restrict__ y,
                                     PRow* __restrict__ z) {
#pragma unroll
    for (int i = 0; i < 4; ++i) {
        if (ZERO) { z[i].r01 = pk2(0, 0); z[i].r23 = pk2(0, 0); z[i].i01 = pk2(0, 0); z[i].i23 = pk2(0, 0); }
        float er0, er1, er2, er3, ei0, ei1, ei2, ei3;
        upk2(x[i].r01, er0, er1); upk2(x[i].r23, er2, er3);
        upk2(x[i].i01, ei0, ei1); upk2(x[i].i23, ei2, ei3);
        caccum(er0, ei0, y[0], z[i]);
        caccum(er1, ei1, y[1], z[i]);
        caccum(er2, ei2, y[2], z[i]);
        caccum(er3, ei3, y[3], z[i]);
    }
}

// ---------------------------------------------------------------------------
// Scalar helpers
__device__ __forceinline__ void cax4(float a, float b, float4 cr, float4 ci,
                                     float4& accr, float4& acci) {
    accr.x = fmaf(a, cr.x, fmaf(-b, ci.x, accr.x));
    acci.x = fmaf(a, ci.x, fmaf( b, cr.x, acci.x));
    accr.y = fmaf(a, cr.y, fmaf(-b, ci.y, accr.y));
    acci.y = fmaf(a, ci.y, fmaf( b, cr.y, acci.y));
    accr.z = fmaf(a, cr.z, fmaf(-b, ci.z, accr.z));
    acci.z = fmaf(a, ci.z, fmaf( b, cr.z, acci.z));
    accr.w = fmaf(a, cr.w, fmaf(-b, ci.w, accr.w));
    acci.w = fmaf(a, ci.w, fmaf( b, cr.w, acci.w));
}

// shuffle one full float4-pair row from lane `src` (every lane passes its own row)
__device__ __forceinline__ void shfl_row(float4 pr, float4 pim, int src,
                                         float4& outr, float4& outi) {
    outr.x = __shfl_sync(0xffffffffu, pr.x, src);
    outr.y = __shfl_sync(0xffffffffu, pr.y, src);
    outr.z = __shfl_sync(0xffffffffu, pr.z, src);
    outr.w = __shfl_sync(0xffffffffu, pr.w, src);
    outi.x = __shfl_sync(0xffffffffu, pim.x, src);
    outi.y = __shfl_sync(0xffffffffu, pim.y, src);
    outi.z = __shfl_sync(0xffffffffu, pim.z, src);
    outi.w = __shfl_sync(0xffffffffu, pim.w, src);
}

// ---------------------------------------------------------------------------
// K0: U = expm(-i*dt*H), degree-4 Taylor via packed f32x2, + FUSED chunk
// product via 3-round shfl_xor tree across the 8 lanes of each chunk.
// NO shared memory, NO barriers.
__global__ void __launch_bounds__(128) k_expm(const float* __restrict__ hr_g,
                                              const float* __restrict__ hi_g) {
    int tid = threadIdx.x;
    int idx = blockIdx.x * 128 + tid;

    const float4* hr4 = reinterpret_cast<const float4*>(hr_g) + (size_t)idx * 4;
    const float4* hi4 = reinterpret_cast<const float4*>(hi_g) + (size_t)idx * 4;

    // A = dt*hi - i*dt*hr
    PRow A[4];
    const u64p pdt = psplat(DT), pndt = psplat(-DT);
#pragma unroll
    for (int i = 0; i < 4; ++i) {
        float4 r = hr4[i], m = hi4[i];
        A[i].r01 = pmul(pdt,  pk2(m.x, m.y));
        A[i].r23 = pmul(pdt,  pk2(m.z, m.w));
        A[i].i01 = pmul(pndt, pk2(r.x, r.y));
        A[i].i23 = pmul(pndt, pk2(r.z, r.w));
    }

    PRow B[4];                   // A^2
    pcmm<true>(A, A, B);

    // M = I/2 + A/6 + A^2/24
    PRow M[4];
    const u64p c6 = psplat(1.0f / 6.0f), c24 = psplat(1.0f / 24.0f);
#pragma unroll
    for (int i = 0; i < 4; ++i) {
        M[i].r01 = pfma(c6, A[i].r01, pmul(c24, B[i].r01));
        M[i].r23 = pfma(c6, A[i].r23, pmul(c24, B[i].r23));
        M[i].i01 = pfma(c6, A[i].i01, pmul(c24, B[i].i01));
        M[i].i23 = pfma(c6, A[i].i23, pmul(c24, B[i].i23));
    }
    M[0].r01 = padd(M[0].r01, pk2(0.5f, 0.0f));
    M[1].r01 = padd(M[1].r01, pk2(0.0f, 0.5f));
    M[2].r23 = padd(M[2].r23, pk2(0.5f, 0.0f));
    M[3].r23 = padd(M[3].r23, pk2(0.0f, 0.5f));

    // E = A + B*M  (into A), then +I
    pcmm<false>(B, M, A);
    A[0].r01 = padd(A[0].r01, pk2(1.0f, 0.0f));
    A[1].r01 = padd(A[1].r01, pk2(0.0f, 1.0f));
    A[2].r23 = padd(A[2].r23, pk2(1.0f, 0.0f));
    A[3].r23 = padd(A[3].r23, pk2(0.0f, 1.0f));

    // store U to global (planar: re[16] then im[16])
    {
        float4* Up = g_U + (size_t)idx * 8;
#pragma unroll
        for (int i = 0; i < 4; ++i) {
            float x0, x1, x2, x3;
            upk2(A[i].r01, x0, x1); upk2(A[i].r23, x2, x3);
            Up[i] = make_float4(x0, x1, x2, x3);
        }
#pragma unroll
        for (int i = 0; i < 4; ++i) {
            float x0, x1, x2, x3;
            upk2(A[i].i01, x0, x1); upk2(A[i].i23, x2, x3);
            Up[4 + i] = make_float4(x0, x1, x2, x3);
        }
    }

    // ---- chunk product: shfl_xor tree over the 8 lanes holding U_0..U_7.
    // Invariant: after round d, every lane holds the ordered product of its
    // 2d-aligned lane-block (newest = highest t on the LEFT).
    PRow P[4];
#pragma unroll
    for (int i = 0; i < 4; ++i) P[i] = A[i];

#pragma unroll
    for (int d = 1; d < 8; d <<= 1) {
        PRow Q[4];
#pragma unroll
        for (int i = 0; i < 4; ++i) {
            Q[i].r01 = __shfl_xor_sync(0xffffffffu, P[i].r01, d);
            Q[i].r23 = __shfl_xor_sync(0xffffffffu, P[i].r23, d);
            Q[i].i01 = __shfl_xor_sync(0xffffffffu, P[i].i01, d);
            Q[i].i23 = __shfl_xor_sync(0xffffffffu, P[i].i23, d);
        }
        bool hi = (tid & d) != 0;
        // conditional swap so result is always P_new = P * Q = higher * lower
#pragma unroll
        for (int i = 0; i < 4; ++i) {
            u64p a, b;
            a = P[i].r01; b = Q[i].r01; P[i].r01 = hi ? a : b; Q[i].r01 = hi ? b : a;
            a = P[i].r23; b = Q[i].r23; P[i].r23 = hi ? a : b; Q[i].r23 = hi ? b : a;
            a = P[i].i01; b = Q[i].i01; P[i].i01 = hi ? a : b; Q[i].i01 = hi ? b : a;
            a = P[i].i23; b = Q[i].i23; P[i].i23 = hi ? a : b; Q[i].i23 = hi ? b : a;
        }
        PRow Z[4];
        pcmm<true>(P, Q, Z);
#pragma unroll
        for (int i = 0; i < 4; ++i) P[i] = Z[i];
    }

    // every lane of the 8-group holds the full product; lane g stores quad g
    // (quads 0-3 = real rows, 4-7 = imag rows) -> warp writes 512B contiguous.
    {
        int g = tid & 7;
        bool gi = (g & 4) != 0;
        u64p s0 = gi ? P[0].i01 : P[0].r01;
        u64p s1 = gi ? P[1].i01 : P[1].r01;
        u64p s2 = gi ? P[2].i01 : P[2].r01;
        u64p s3 = gi ? P[3].i01 : P[3].r01;
        u64p t0 = gi ? P[0].i23 : P[0].r23;
        u64p t1 = gi ? P[1].i23 : P[1].r23;
        u64p t2 = gi ? P[2].i23 : P[2].r23;
        u64p t3 = gi ? P[3].i23 : P[3].r23;
        u64p lo = (g & 2) ? ((g & 1) ? s3 : s2) : ((g & 1) ? s1 : s0);
        u64p hi2 = (g & 2) ? ((g & 1) ? t3 : t2) : ((g & 1) ? t1 : t0);
        float x0, x1, x2, x3;
        upk2(lo, x0, x1); upk2(hi2, x2, x3);
        int chunk = idx >> 3;
        g_P[(size_t)chunk * 8 + g] = make_float4(x0, x1, x2, x3);
    }
}

// ---------------------------------------------------------------------------
// K2: TWO-LEVEL row-parallel scan per batch. 1024 threads = 256 chunks x 4 rows.
#define TOFF 288   // T_B offset (T matrices stride 9 quads; 32*9=288 per buffer)

__global__ void __launch_bounds__(1024) k_scan(const float* __restrict__ s0r_g,
                                               const float* __restrict__ s0i_g) {
    __shared__ float4 sh[CC * 12];   // 48KB; quads [0,576) double as T_A/T_B
    int b = blockIdx.x;
    int tid = threadIdx.x;
    int e = tid >> 2, i = tid & 3;
    int lane = tid & 31;
    int el = lane >> 2;              // local chunk within warp (0..7)
    int g = e >> 3;                  // group (= warp id, 0..31)

    const float4* Pg = g_P + ((size_t)b * CC + e) * 8;
    float4 pr = Pg[i], pim = Pg[4 + i];

    // ---- L1: warp-local KS over 8 (rows fetched via shfl)
#pragma unroll
    for (int d = 1; d < 8; d <<= 1) {
        int srcb = ((el >= d) ? (el - d) : 0) << 2;
        float4 l0r, l0i, l1r, l1i, l2r, l2i, l3r, l3i;
        shfl_row(pr, pim, srcb + 0, l0r, l0i);
        shfl_row(pr, pim, srcb + 1, l1r, l1i);
        shfl_row(pr, pim, srcb + 2, l2r, l2i);
        shfl_row(pr, pim, srcb + 3, l3r, l3i);
        if (el >= d) {
            float4 nr = make_float4(0, 0, 0, 0), ni = make_float4(0, 0, 0, 0);
            cax4(pr.x, pim.x, l0r, l0i, nr, ni);
            cax4(pr.y, pim.y, l1r, l1i, nr, ni);
            cax4(pr.z, pim.z, l2r, l2i, nr, ni);
            cax4(pr.w, pim.w, l3r, l3i, nr, ni);
            pr = nr; pim = ni;
        }
    }

    // ---- publish group totals (el==7) into T_A (stride 9 quads per matrix)
    if (el == 7) {
        sh[g * 9 + i] = pr;
        sh[g * 9 + 4 + i] = pim;
    }
    __syncthreads();

    // ---- L2: KS over 32 totals, 128 threads, 5 rounds, double-buffered
    if (tid < 128) {
        int g2 = tid >> 2, i2 = tid & 3;
        int rb = 0;
#pragma unroll
        for (int d = 1; d < 32; d <<= 1) {
            const float4* src = sh + rb;
            float4* dst = sh + (TOFF - rb);
            float4 qr = src[g2 * 9 + i2], qi = src[g2 * 9 + 4 + i2];
            if (g2 >= d) {
                const float4* nb = src + (size_t)(g2 - d) * 9;
                float4 nr = make_float4(0, 0, 0, 0), ni = make_float4(0, 0, 0, 0);
                cax4(qr.x, qi.x, nb[0], nb[4], nr, ni);
                cax4(qr.y, qi.y, nb[1], nb[5], nr, ni);
                cax4(qr.z, qi.z, nb[2], nb[6], nr, ni);
                cax4(qr.w, qi.w, nb[3], nb[7], nr, ni);
                qr = nr; qi = ni;
            }
            dst[g2 * 9 + i2] = qr;
            dst[g2 * 9 + 4 + i2] = qi;
            asm volatile("bar.sync 1, 128;" ::: "memory");
            rb = TOFF - rb;
        }
    }
    __syncthreads();
    // G (inclusive group prefixes) now at sh + TOFF

    // ---- inclusive prefix: Q_e * G_{g-1}
    if (g > 0) {
        const float4* nb = sh + TOFF + (size_t)(g - 1) * 9;
        float4 nr = make_float4(0, 0, 0, 0), ni = make_float4(0, 0, 0, 0);
        cax4(pr.x, pim.x, nb[0], nb[4], nr, ni);
        cax4(pr.y, pim.y, nb[1], nb[5], nr, ni);
        cax4(pr.z, pim.z, nb[2], nb[6], nr, ni);
        cax4(pr.w, pim.w, nb[3], nb[7], nr, ni);
        pr = nr; pim = ni;
    }
    __syncthreads();   // everyone done reading T before overwriting sh below

    // ---- publish inclusive rows (XOR-swizzled layout)
    int es = e & 7;
    {
        float4* me = sh + e * 12;
        me[i ^ es] = pr;
        me[(4 + i) ^ es] = pim;
    }
    __syncthreads();

    // ---- V_e = Prefix_{e-1} * S0  (V_0 = S0)
    const float4* r4 = reinterpret_cast<const float4*>(s0r_g) + (size_t)b * 4;
    const float4* i4 = reinterpret_cast<const float4*>(s0i_g) + (size_t)b * 4;
    float4 s0r0 = r4[0], s0r1 = r4[1], s0r2 = r4[2], s0r3 = r4[3];
    float4 s0i0 = i4[0], s0i1 = i4[1], s0i2 = i4[2], s0i3 = i4[3];

    float4 vr, vi;
    if (e == 0) {
        vr = (i == 0) ? s0r0 : (i == 1) ? s0r1 : (i == 2) ? s0r2 : s0r3;
        vi = (i == 0) ? s0i0 : (i == 1) ? s0i1 : (i == 2) ? s0i2 : s0i3;
    } else {
        int ens = (e - 1) & 7;
        const float4* nb = sh + (e - 1) * 12;
        float4 qr = nb[i ^ ens];
        float4 qi = nb[(4 + i) ^ ens];
        vr = make_float4(0, 0, 0, 0); vi = make_float4(0, 0, 0, 0);
        cax4(qr.x, qi.x, s0r0, s0i0, vr, vi);
        cax4(qr.y, qi.y, s0r1, s0i1, vr, vi);
        cax4(qr.z, qi.z, s0r2, s0i2, vr, vi);
        cax4(qr.w, qi.w, s0r3, s0i3, vr, vi);
    }
    float4* Sg = g_S + ((size_t)b * CC + e) * 8;
    Sg[i] = vr;
    Sg[4 + i] = vi;
}

// ---------------------------------------------------------------------------
// K3: ROW-parallel apply, BATCH-MAJOR mapping: warp's 8 chunk-groups are 8
// consecutive b with the same c -> each STG.128 is part of a 512B-contiguous
// warp store. State in smem double-buffered, stride 13 (conflict-free).
#define SSTR 13

__global__ void __launch_bounds__(128) k_apply(float* __restrict__ out) {
    __shared__ float4 sS[2][32 * SSTR];      // 13,312 B

    int tid = threadIdx.x;
    int cl = tid >> 2, i = tid & 3;
    int gidx = blockIdx.x * 32 + cl;         // b-fast ordering
    int b = gidx & (BB - 1);
    int c = gidx >> 7;                       // / BB
    int idx = b * CC + c;                    // chunk index in g_U/g_S

    {   // stage incoming state rows
        const float4* Sg = g_S + (size_t)idx * 8;
        sS[0][cl * SSTR + i] = Sg[i];
        sS[0][cl * SSTR + 4 + i] = Sg[4 + i];
    }

    const float4* Ug = g_U + (size_t)idx * 64;
    float4 ur = Ug[i], ui = Ug[4 + i];       // prefetch l=0

    __syncwarp();

    const size_t imag_off = (size_t)TT * BB * 16;
    float* ob = out + (((size_t)c * LL) * BB + b) * 16 + i * 4;

#pragma unroll
    for (int l = 0; l < LL; ++l) {
        float4 nur, nui;
        if (l < LL - 1) {
            nur = Ug[(l + 1) * 8 + i];
            nui = Ug[(l + 1) * 8 + 4 + i];
        }

        const int cur = l & 1;
        float4 s0r = sS[cur][cl * SSTR + 0];
        float4 s1r = sS[cur][cl * SSTR + 1];
        float4 s2r = sS[cur][cl * SSTR + 2];
        float4 s3r = sS[cur][cl * SSTR + 3];
        float4 s0i = sS[cur][cl * SSTR + 4];
        float4 s1i = sS[cur][cl * SSTR + 5];
        float4 s2i = sS[cur][cl * SSTR + 6];
        float4 s3i = sS[cur][cl * SSTR + 7];

        float4 nr = make_float4(0, 0, 0, 0), ni = make_float4(0, 0, 0, 0);
        cax4(ur.x, ui.x, s0r, s0i, nr, ni);
        cax4(ur.y, ui.y, s1r, s1i, nr, ni);
        cax4(ur.z, ui.z, s2r, s2i, nr, ni);
        cax4(ur.w, ui.w, s3r, s3i, nr, ni);

        if (l < LL - 1) {
            sS[cur ^ 1][cl * SSTR + i] = nr;
            sS[cur ^ 1][cl * SSTR + 4 + i] = ni;
        }

        float* op = ob + (size_t)l * BB * 16;
        __stcs(reinterpret_cast<float4*>(op), nr);
        __stcs(reinterpret_cast<float4*>(op + imag_off), ni);

        __syncwarp();
        ur = nur; ui = nui;
    }
}

// ---------------------------------------------------------------------------
extern "C" void kernel_launch(void* const* d_in, const int* in_sizes, int n_in,
                              void* d_out, int out_size) {
    const float* h_real = (const float*)d_in[0];
    const float* h_imag = (const float*)d_in[1];
    const float* s_real = (const float*)d_in[2];
    const float* s_imag = (const float*)d_in[3];
    float* out = (float*)d_out;

    k_expm<<<NM / 128, 128>>>(h_real, h_imag);
    k_scan<<<BB, CC * 4>>>(s_real, s_imag);
    k_apply<<<(BB * CC) / 32, 128>>>(out);
}